// round 16
// baseline (speedup 1.0000x reference)
#include <cuda_runtime.h>
#include <cstdint>
#include <cstddef>

#define T_STEPS 512
#define BATCH   64
#define HID     512
#define INP     512
#define G4      2048            // 4*HID
#define HPAD    516             // padded row stride (floats) to break bank conflicts
#define NBLK    128             // persistent grid size
#define NTH     256             // threads

// ---------------- device scratch (static; no runtime allocation) ----------------
__device__ float g_hbuf[2][BATCH * HID];               // ping-pong h
__device__ unsigned int g_bar;                         // grid barrier counter

// ---------------- helpers ----------------
__device__ __forceinline__ void ffma2(unsigned long long &c, unsigned long long a,
                                      unsigned long long b) {
    asm("fma.rn.f32x2 %0, %1, %2, %0;" : "+l"(c) : "l"(a), "l"(b));
}
__device__ __forceinline__ float hsum2(unsigned long long v) {
    float lo, hi;
    asm("mov.b64 {%0, %1}, %2;" : "=f"(lo), "=f"(hi) : "l"(v));
    return lo + hi;
}

// =================================================================================
// Fused persistent LSTM: 128 blocks x 256 threads (R2-proven shape + barrier).
// tidL = tid & 127 -> jj (8 J) x bg (16 batch pairs); kh = tid>>7 splits K in half.
// Each step t: dot h(t)·W_hh  AND  x(t+1)·W_ih (fills the fma-pipe bubbles).
// xg never touches gmem: it is produced into the xr registers used next step.
// W_hh + W_ih slices cached in SMEM once; h staged from L2 each step.
// =================================================================================
__global__ __launch_bounds__(NTH) void lstm_fused_kernel(
        const float* __restrict__ x,   const float* __restrict__ h0,
        const float* __restrict__ c0,  const float* __restrict__ Wih,
        const float* __restrict__ Whh, const float* __restrict__ bih,
        const float* __restrict__ bhh, float* __restrict__ out, int write_tail) {
    extern __shared__ __align__(16) float smem[];
    float* swh = smem;                       // 32 rows x HPAD (W_hh slice)
    float* swi = smem + 32 * HPAD;           // 32 rows x HPAD (W_ih slice)
    float* sh  = smem + 64 * HPAD;           // 32 rows x HPAD (h slice)
    float* red = smem + 96 * HPAD;           // 128 x 16 floats (kh=1 partials)

    const int tid   = threadIdx.x;
    const int tidL  = tid & 127;
    const int kh    = tid >> 7;          // K-half: 0 or 1
    const int jg    = blockIdx.x & 63;
    const int bhalf = blockIdx.x >> 6;
    const int b_base = bhalf * 32;
    const int jj = tidL & 7;             // hidden unit within group
    const int bg = tidL >> 3;            // 0..15 (batch pair)
    const int J  = jg * 8 + jj;          // global hidden index
    const int b0 = b_base + bg * 2;

    // one-time W slices: rows r = gate*8 + jj_local -> global row gate*HID + J
    #pragma unroll 4
    for (int q = tid; q < 32 * 128; q += NTH) {
        int r  = q >> 7;
        int k4 = (q & 127) * 4;
        int gr = (r >> 3) * HID + jg * 8 + (r & 7);
        *(float4*)(swh + r * HPAD + k4) =
            __ldcg((const float4*)(Whh + (size_t)gr * HID + k4));
        *(float4*)(swi + r * HPAD + k4) =
            __ldcg((const float4*)(Wih + (size_t)gr * INP + k4));
    }

    float cc[2] = {0.f, 0.f};
    float hh[2] = {0.f, 0.f};
    float bs[4] = {0.f, 0.f, 0.f, 0.f};
    if (kh == 0) {
        cc[0] = c0[(size_t)b0 * HID + J];
        cc[1] = c0[(size_t)(b0 + 1) * HID + J];
        #pragma unroll
        for (int g = 0; g < 4; ++g)
            bs[g] = bih[g * HID + J] + bhh[g * HID + J];
    }

    const int pbase = kh * 128;          // u64 offset of this thread's K-half
    const unsigned long long* wu[4];
    const unsigned long long* wiu[4];
    #pragma unroll
    for (int g = 0; g < 4; ++g) {
        wu[g]  = (const unsigned long long*)(swh + (g * 8 + jj) * HPAD) + pbase;
        wiu[g] = (const unsigned long long*)(swi + (g * 8 + jj) * HPAD) + pbase;
    }
    const unsigned long long* hu0 =
        (const unsigned long long*)(sh + (bg * 2) * HPAD) + pbase;
    const unsigned long long* hu1 =
        (const unsigned long long*)(sh + (bg * 2 + 1) * HPAD) + pbase;

    __syncthreads();                     // W slices visible

    float xr[4][2];                      // xg for the CURRENT step (registers only)

    // ---------------- prologue: xg[0] = x[:,0,:]·W_ih (k-half split) --------------
    {
        unsigned long long xA[2][4], xB[2][4];
        #pragma unroll
        for (int bi = 0; bi < 2; ++bi)
            #pragma unroll
            for (int g = 0; g < 4; ++g) { xA[bi][g] = 0ull; xB[bi][g] = 0ull; }
        const unsigned long long* xp0 =
            (const unsigned long long*)(x + ((size_t)b0 * T_STEPS + 0) * INP) + pbase;
        const unsigned long long* xp1 =
            (const unsigned long long*)(x + ((size_t)(b0 + 1) * T_STEPS + 0) * INP) + pbase;
        #pragma unroll 8
        for (int p = 0; p < 128; p += 2) {
            ulonglong2 xva = __ldg((const ulonglong2*)(xp0 + p));
            ulonglong2 xvb = __ldg((const ulonglong2*)(xp1 + p));
            #pragma unroll
            for (int g = 0; g < 4; ++g) {
                ulonglong2 wv = *(const ulonglong2*)(wiu[g] + p);
                ffma2(xA[0][g], xva.x, wv.x);
                ffma2(xB[0][g], xva.y, wv.y);
                ffma2(xA[1][g], xvb.x, wv.x);
                ffma2(xB[1][g], xvb.y, wv.y);
            }
        }
        float xp[2][4];
        #pragma unroll
        for (int bi = 0; bi < 2; ++bi)
            #pragma unroll
            for (int g = 0; g < 4; ++g)
                xp[bi][g] = hsum2(xA[bi][g]) + hsum2(xB[bi][g]);
        if (kh == 1) {
            float4* dst = (float4*)(red + tidL * 16);
            dst[2] = make_float4(xp[0][0], xp[0][1], xp[0][2], xp[0][3]);
            dst[3] = make_float4(xp[1][0], xp[1][1], xp[1][2], xp[1][3]);
        }
        __syncthreads();
        if (kh == 0) {
            const float4* src = (const float4*)(red + tidL * 16);
            float4 r0 = src[2], r1 = src[3];
            xr[0][0] = xp[0][0] + r0.x + bs[0];
            xr[1][0] = xp[0][1] + r0.y + bs[1];
            xr[2][0] = xp[0][2] + r0.z + bs[2];
            xr[3][0] = xp[0][3] + r0.w + bs[3];
            xr[0][1] = xp[1][0] + r1.x + bs[0];
            xr[1][1] = xp[1][1] + r1.y + bs[1];
            xr[2][1] = xp[1][2] + r1.z + bs[2];
            xr[3][1] = xp[1][3] + r1.w + bs[3];
        }
    }

    // ---------------- main loop ---------------------------------------------------
    for (int t = 0; t < T_STEPS; ++t) {
        // stage h slice (L2 reads; __ldcg avoids stale L1)
        const float* hsrc = (t == 0) ? h0 : g_hbuf[t & 1];
        #pragma unroll 8
        for (int q = tid; q < 32 * 128; q += NTH) {
            int bb = q >> 7;
            int k4 = (q & 127) * 4;
            *(float4*)(sh + bb * HPAD + k4) =
                __ldcg((const float4*)(hsrc + (size_t)(b_base + bb) * HID + k4));
        }
        __syncthreads();

        const int tn = (t + 1 < T_STEPS) ? (t + 1) : t;   // clamped next timestep
        const unsigned long long* xp0 =
            (const unsigned long long*)(x + ((size_t)b0 * T_STEPS + tn) * INP) + pbase;
        const unsigned long long* xp1 =
            (const unsigned long long*)(x + ((size_t)(b0 + 1) * T_STEPS + tn) * INP) + pbase;

        unsigned long long aA[2][4], aB[2][4];   // h-dot accumulators
        unsigned long long xA[2][4], xB[2][4];   // xg-dot accumulators
        #pragma unroll
        for (int bi = 0; bi < 2; ++bi)
            #pragma unroll
            for (int g = 0; g < 4; ++g) {
                aA[bi][g] = 0ull; aB[bi][g] = 0ull;
                xA[bi][g] = 0ull; xB[bi][g] = 0ull;
            }

        // fused dot: h(t)·W_hh  +  x(t+1)·W_ih, 4 k per iter, packed f32x2
        #pragma unroll 4
        for (int p = 0; p < 128; p += 2) {
            ulonglong2 hva = *(const ulonglong2*)(hu0 + p);
            ulonglong2 hvb = *(const ulonglong2*)(hu1 + p);
            ulonglong2 xva = __ldg((const ulonglong2*)(xp0 + p));
            ulonglong2 xvb = __ldg((const ulonglong2*)(xp1 + p));
            #pragma unroll
            for (int g = 0; g < 4; ++g) {
                ulonglong2 wv  = *(const ulonglong2*)(wu[g] + p);
                ulonglong2 wiv = *(const ulonglong2*)(wiu[g] + p);
                ffma2(aA[0][g], hva.x, wv.x);
                ffma2(aB[0][g], hva.y, wv.y);
                ffma2(aA[1][g], hvb.x, wv.x);
                ffma2(aB[1][g], hvb.y, wv.y);
                ffma2(xA[0][g], xva.x, wiv.x);
                ffma2(xB[0][g], xva.y, wiv.y);
                ffma2(xA[1][g], xvb.x, wiv.x);
                ffma2(xB[1][g], xvb.y, wiv.y);
            }
        }

        float part[2][4], xprt[2][4];
        #pragma unroll
        for (int bi = 0; bi < 2; ++bi)
            #pragma unroll
            for (int g = 0; g < 4; ++g) {
                part[bi][g] = hsum2(aA[bi][g]) + hsum2(aB[bi][g]);
                xprt[bi][g] = hsum2(xA[bi][g]) + hsum2(xB[bi][g]);
            }

        // kh=1 writes both partial sets into dedicated scratch
        if (kh == 1) {
            float4* dst = (float4*)(red + tidL * 16);
            dst[0] = make_float4(part[0][0], part[0][1], part[0][2], part[0][3]);
            dst[1] = make_float4(part[1][0], part[1][1], part[1][2], part[1][3]);
            dst[2] = make_float4(xprt[0][0], xprt[0][1], xprt[0][2], xprt[0][3]);
            dst[3] = make_float4(xprt[1][0], xprt[1][1], xprt[1][2], xprt[1][3]);
        }
        __syncthreads();

        if (kh == 0) {
            const float4* src = (const float4*)(red + tidL * 16);
            float4 r0 = src[0], r1 = src[1];
            part[0][0] += r0.x; part[0][1] += r0.y;
            part[0][2] += r0.z; part[0][3] += r0.w;
            part[1][0] += r1.x; part[1][1] += r1.y;
            part[1][2] += r1.z; part[1][3] += r1.w;

            float* hdst = g_hbuf[(t + 1) & 1];
            #pragma unroll
            for (int bi = 0; bi < 2; ++bi) {
                float pi = part[bi][0] + xr[0][bi];
                float pf = part[bi][1] + xr[1][bi];
                float pg = part[bi][2] + xr[2][bi];
                float po = part[bi][3] + xr[3][bi];
                float ii = 1.f / (1.f + __expf(-pi));
                float ff = 1.f / (1.f + __expf(-pf));
                float gg = tanhf(pg);
                float oo = 1.f / (1.f + __expf(-po));
                float c  = ff * cc[bi] + ii * gg;
                cc[bi]   = c;
                float h  = oo * tanhf(c);
                hh[bi]   = h;
                hdst[(size_t)(b0 + bi) * HID + J] = h;
                out[((size_t)(b0 + bi) * T_STEPS + t) * HID + J] = h;
            }

            // xg for step t+1 straight into registers
            float4 s2 = src[2], s3 = src[3];
            xr[0][0] = xprt[0][0] + s2.x + bs[0];
            xr[1][0] = xprt[0][1] + s2.y + bs[1];
            xr[2][0] = xprt[0][2] + s2.z + bs[2];
            xr[3][0] = xprt[0][3] + s2.w + bs[3];
            xr[0][1] = xprt[1][0] + s3.x + bs[0];
            xr[1][1] = xprt[1][1] + s3.y + bs[1];
            xr[2][1] = xprt[1][2] + s3.z + bs[2];
            xr[3][1] = xprt[1][3] + s3.w + bs[3];
        }

        // ---- grid barrier: R2-proven protocol, verbatim ----
        __threadfence();
        __syncthreads();
        if (tid == 0) {
            atomicAdd(&g_bar, 1u);
            unsigned target = (unsigned)(t + 1) * NBLK;
            while (*((volatile unsigned*)&g_bar) < target) { }
            __threadfence();
        }
        __syncthreads();
    }

    // tail outputs (h_T, c_T) from registers
    if (write_tail && kh == 0) {
        float* outH = out + (size_t)BATCH * T_STEPS * HID;
        float* outC = outH + BATCH * HID;
        #pragma unroll
        for (int bi = 0; bi < 2; ++bi) {
            outH[(size_t)(b0 + bi) * HID + J] = hh[bi];
            outC[(size_t)(b0 + bi) * HID + J] = cc[bi];
        }
    }
}

// =================================================================================
extern "C" void kernel_launch(void* const* d_in, const int* in_sizes, int n_in,
                              void* d_out, int out_size) {
    const float* x   = (const float*)d_in[0];
    const float* h0  = (const float*)d_in[1];
    const float* c0  = (const float*)d_in[2];
    const float* Wih = (const float*)d_in[3];
    const float* Whh = (const float*)d_in[4];
    const float* bih = (const float*)d_in[5];
    const float* bhh = (const float*)d_in[6];
    float* out = (float*)d_out;

    const size_t total_elems = (size_t)BATCH * T_STEPS * HID + 2 * (size_t)BATCH * HID;
    const int write_tail = ((size_t)out_size >= total_elems) ? 1 : 0;

    const int smem_bytes = (96 * HPAD + 128 * 16) * (int)sizeof(float);  // ~202 KB
    cudaFuncSetAttribute(lstm_fused_kernel, cudaFuncAttributeMaxDynamicSharedMemorySize,
                         smem_bytes);

    // reset grid-barrier counter (captured as a memset node; runs every replay)
    void* barAddr = nullptr;
    cudaGetSymbolAddress(&barAddr, g_bar);
    cudaMemsetAsync(barAddr, 0, sizeof(unsigned int));

    lstm_fused_kernel<<<NBLK, NTH, smem_bytes>>>(x, h0, c0, Wih, Whh, bih, bhh,
                                                 out, write_tail);
}

// round 17
// speedup vs baseline: 1.4752x; 1.4752x over previous
#include <cuda_runtime.h>
#include <cstdint>
#include <cstddef>

#define T_STEPS 512
#define BATCH   64
#define HID     512
#define INP     512
#define G4      2048            // 4*HID
#define HPAD    516             // padded row stride (floats) to break bank conflicts
#define NBLK    128             // persistent grid size
#define NCHUNK  256             // gemm m-chunks (2 timesteps each)

// ---------------- device scratch (static; no runtime allocation) ----------------
__device__ float g_xg[(size_t)T_STEPS * BATCH * G4];   // [T][B][4H]
__device__ float g_hbuf[2][BATCH * HID];               // ping-pong h
__device__ unsigned int g_bar;                         // grid barrier counter
__device__ unsigned int g_xgflag[NCHUNK];              // per-t-chunk done counters (x32)

// ---------------- f32x2 helpers ----------------
__device__ __forceinline__ void ffma2(unsigned long long &c, unsigned long long a,
                                      unsigned long long b) {
    asm("fma.rn.f32x2 %0, %1, %2, %0;" : "+l"(c) : "l"(a), "l"(b));
}
__device__ __forceinline__ float hsum2(unsigned long long v) {
    float lo, hi;
    asm("mov.b64 {%0, %1}, %2;" : "=f"(lo), "=f"(hi) : "l"(v));
    return lo + hi;
}

// =================================================================================
// Kernel 1: xg[t][b][g] = x[b,t,:] . W_ih[g,:] + (b_ih + b_hh), T-MAJOR m ordering:
// m = t*64 + b, so blockIdx.y covers timesteps [2y, 2y+2) for ALL batches.
// After its stores, each block bumps g_xgflag[y]; chunk y ready when flag==32.
// =================================================================================
__global__ __launch_bounds__(256) void xg_gemm_kernel(
        const float* __restrict__ x, const float* __restrict__ Wih,
        const float* __restrict__ bih, const float* __restrict__ bhh) {
    __shared__ __align__(16) float2 As2[8][128];   // [k_pair][m]
    __shared__ __align__(16) float2 Bs2[8][64];    // [k_pair][n]

    const int tid = threadIdx.x;
    const int tx = tid & 15;        // n-dim thread coord (0..15)
    const int ty = tid >> 4;        // m-dim thread coord (0..15)
    const int m0 = blockIdx.y * 128;
    const int n0 = blockIdx.x * 64;

    unsigned long long acc[8][4];
    #pragma unroll
    for (int i = 0; i < 8; ++i)
        #pragma unroll
        for (int j = 0; j < 4; ++j) acc[i][j] = 0ull;

    for (int k0 = 0; k0 < INP; k0 += 16) {
        #pragma unroll
        for (int it = 0; it < 2; ++it) {
            int fl  = tid + it * 256;
            int row = fl >> 2;
            int kq  = fl & 3;
            int m   = m0 + row;
            int tt  = m >> 6;               // timestep
            int bb  = m & 63;               // batch
            const float4 v = *(const float4*)(
                x + ((size_t)bb * T_STEPS + tt) * INP + k0 + kq * 4);
            As2[kq * 2    ][row] = make_float2(v.x, v.y);
            As2[kq * 2 + 1][row] = make_float2(v.z, v.w);
        }
        {
            int row = tid >> 2;
            int kq  = tid & 3;
            const float4 v = *(const float4*)(Wih + (size_t)(n0 + row) * INP + k0 + kq * 4);
            Bs2[kq * 2    ][row] = make_float2(v.x, v.y);
            Bs2[kq * 2 + 1][row] = make_float2(v.z, v.w);
        }
        __syncthreads();

        #pragma unroll
        for (int kk = 0; kk < 8; ++kk) {
            unsigned long long a[8], b[4];
            #pragma unroll
            for (int i = 0; i < 4; ++i) {
                ulonglong2 t2 = *(const ulonglong2*)&As2[kk][ty * 8 + i * 2];
                a[i * 2] = t2.x; a[i * 2 + 1] = t2.y;
            }
            #pragma unroll
            for (int j = 0; j < 2; ++j) {
                ulonglong2 t2 = *(const ulonglong2*)&Bs2[kk][tx * 4 + j * 2];
                b[j * 2] = t2.x; b[j * 2 + 1] = t2.y;
            }
            #pragma unroll
            for (int i = 0; i < 8; ++i)
                #pragma unroll
                for (int j = 0; j < 4; ++j)
                    ffma2(acc[i][j], a[i], b[j]);
        }
        __syncthreads();
    }

    const int nb = n0 + tx * 4;
    float bj[4];
    #pragma unroll
    for (int j = 0; j < 4; ++j) bj[j] = bih[nb + j] + bhh[nb + j];

    #pragma unroll
    for (int i = 0; i < 8; ++i) {
        int m  = m0 + ty * 8 + i;
        int tt = m >> 6;          // timestep (t-major ordering)
        int bb = m & 63;          // batch
        float4 r;
        r.x = hsum2(acc[i][0]) + bj[0];
        r.y = hsum2(acc[i][1]) + bj[1];
        r.z = hsum2(acc[i][2]) + bj[2];
        r.w = hsum2(acc[i][3]) + bj[3];
        *(float4*)(g_xg + ((size_t)tt * BATCH + bb) * G4 + nb) = r;
    }

    // announce chunk completion (release: one cumulative fence after block sync)
    __syncthreads();
    if (tid == 0) {
        __threadfence();
        atomicAdd(&g_xgflag[blockIdx.y], 1u);
    }
}

// =================================================================================
// Kernel 2: persistent recurrence — R2-proven 4138us version, byte-exact, plus a
// tid0 wait on g_xgflag[t>>1] (xg producer flag) folded into the post-stage sync.
// 128 blocks x 256 threads; kh = tid>>7 splits K in half.
// =================================================================================
__global__ __launch_bounds__(256) void lstm_rec_kernel(
        const float* __restrict__ h0, const float* __restrict__ c0,
        const float* __restrict__ Whh, float* __restrict__ out, int write_tail) {
    extern __shared__ __align__(16) float smem[];
    float* sw = smem;                    // 32 rows x HPAD  (W slice)
    float* sh = smem + 32 * HPAD;        // 32 rows x HPAD  (h slice, also red scratch)

    const int tid   = threadIdx.x;
    const int tidL  = tid & 127;
    const int kh    = tid >> 7;          // K-half: 0 or 1
    const int jg    = blockIdx.x & 63;
    const int bhalf = blockIdx.x >> 6;
    const int b_base = bhalf * 32;
    const int jj = tidL & 7;             // hidden unit within group
    const int bg = tidL >> 3;            // 0..15 (batch pair group)
    const int J  = jg * 8 + jj;          // global hidden index

    // one-time W_hh slice load: rows r = gate*8 + jj_local -> global row gate*HID + J
    #pragma unroll 8
    for (int q = tid; q < 32 * 128; q += 256) {
        int r  = q >> 7;
        int k4 = (q & 127) * 4;
        int gr = (r >> 3) * HID + jg * 8 + (r & 7);
        *(float4*)(sw + r * HPAD + k4) =
            __ldcg((const float4*)(Whh + (size_t)gr * HID + k4));
    }

    const int b0 = b_base + bg * 2;
    float cc[2] = {0.f, 0.f};
    if (kh == 0) {
        cc[0] = c0[(size_t)b0 * HID + J];
        cc[1] = c0[(size_t)(b0 + 1) * HID + J];
    }

    const int pbase = kh * 128;          // u64 offset of this warp's K-half
    const unsigned long long* wu[4];
    #pragma unroll
    for (int g = 0; g < 4; ++g)
        wu[g] = (const unsigned long long*)(sw + (g * 8 + jj) * HPAD) + pbase;
    const unsigned long long* hu0 =
        (const unsigned long long*)(sh + (bg * 2) * HPAD) + pbase;
    const unsigned long long* hu1 =
        (const unsigned long long*)(sh + (bg * 2 + 1) * HPAD) + pbase;

    float* outH = out + (size_t)BATCH * T_STEPS * HID;
    float* outC = outH + BATCH * HID;

    for (int t = 0; t < T_STEPS; ++t) {
        const float* hsrc = (t == 0) ? h0 : g_hbuf[t & 1];
        // stage h slice (L2 reads; __ldcg avoids stale L1)
        #pragma unroll 8
        for (int q = tid; q < 32 * 128; q += 256) {
            int bb = q >> 7;
            int k4 = (q & 127) * 4;
            *(float4*)(sh + bb * HPAD + k4) =
                __ldcg((const float4*)(hsrc + (size_t)(b_base + bb) * HID + k4));
        }
        // wait for xg chunk for this timestep (producer gemm runs concurrently).
        // tid0 polls (monotonic counter, no collectives); others arrive at the sync.
        if (tid == 0) {
            while (*((volatile unsigned*)&g_xgflag[t >> 1]) < 32u) { }
            __threadfence();             // acquire side for xg reads below
        }
        __syncthreads();

        // prefetch xg for this thread's 8 outputs (kh=0 only)
        float xr[4][2];
        if (kh == 0) {
            size_t xbase = ((size_t)t * BATCH + b0) * G4 + J;
            #pragma unroll
            for (int g = 0; g < 4; ++g) {
                xr[g][0] = g_xg[xbase + g * HID];
                xr[g][1] = g_xg[xbase + G4 + g * HID];
            }
        }

        unsigned long long aA[2][4], aB[2][4];
        #pragma unroll
        for (int bi = 0; bi < 2; ++bi)
            #pragma unroll
            for (int g = 0; g < 4; ++g) { aA[bi][g] = 0ull; aB[bi][g] = 0ull; }

        // dot over this warp's K-half: 4 k per iter, packed f32x2
        #pragma unroll 8
        for (int p = 0; p < 128; p += 2) {
            ulonglong2 hva = *(const ulonglong2*)(hu0 + p);
            ulonglong2 hvb = *(const ulonglong2*)(hu1 + p);
            #pragma unroll
            for (int g = 0; g < 4; ++g) {
                ulonglong2 wv = *(const ulonglong2*)(wu[g] + p);
                ffma2(aA[0][g], hva.x, wv.x);
                ffma2(aB[0][g], hva.y, wv.y);
                ffma2(aA[1][g], hvb.x, wv.x);
                ffma2(aB[1][g], hvb.y, wv.y);
            }
        }

        // combine halves of each accumulator into one float per output
        float part[2][4];
        #pragma unroll
        for (int bi = 0; bi < 2; ++bi)
            #pragma unroll
            for (int g = 0; g < 4; ++g)
                part[bi][g] = hsum2(aA[bi][g]) + hsum2(aB[bi][g]);

        // cross-warp (K-half) reduction through SMEM scratch (reuse sh region)
        __syncthreads();                 // dot loop done reading sh
        float* red = sh;                 // 128 threads x 8 floats
        if (kh == 1) {
            float4* dst = (float4*)(red + tidL * 8);
            dst[0] = make_float4(part[0][0], part[0][1], part[0][2], part[0][3]);
            dst[1] = make_float4(part[1][0], part[1][1], part[1][2], part[1][3]);
        }
        __syncthreads();

        if (kh == 0) {
            const float4* src = (const float4*)(red + tidL * 8);
            float4 r0 = src[0], r1 = src[1];
            part[0][0] += r0.x; part[0][1] += r0.y; part[0][2] += r0.z; part[0][3] += r0.w;
            part[1][0] += r1.x; part[1][1] += r1.y; part[1][2] += r1.z; part[1][3] += r1.w;

            float* hdst = g_hbuf[(t + 1) & 1];
            #pragma unroll
            for (int bi = 0; bi < 2; ++bi) {
                float pi = part[bi][0] + xr[0][bi];
                float pf = part[bi][1] + xr[1][bi];
                float pg = part[bi][2] + xr[2][bi];
                float po = part[bi][3] + xr[3][bi];
                float ii = 1.f / (1.f + __expf(-pi));
                float ff = 1.f / (1.f + __expf(-pf));
                float gg = tanhf(pg);
                float oo = 1.f / (1.f + __expf(-po));
                float c  = ff * cc[bi] + ii * gg;
                cc[bi]   = c;
                float h  = oo * tanhf(c);
                int b    = b0 + bi;
                hdst[(size_t)b * HID + J] = h;
                out[((size_t)b * T_STEPS + t) * HID + J] = h;
                if (write_tail && t == T_STEPS - 1) {
                    outH[(size_t)b * HID + J] = h;
                    outC[(size_t)b * HID + J] = c;
                }
            }
            __threadfence();             // make h stores visible before barrier signal
        }

        // ---- grid barrier (all 128 blocks co-resident) ----
        __syncthreads();
        if (tid == 0) {
            atomicAdd(&g_bar, 1u);
            unsigned target = (unsigned)(t + 1) * NBLK;
            while (*((volatile unsigned*)&g_bar) < target) { }
            __threadfence();
        }
        __syncthreads();
    }
}

// =================================================================================
extern "C" void kernel_launch(void* const* d_in, const int* in_sizes, int n_in,
                              void* d_out, int out_size) {
    const float* x   = (const float*)d_in[0];
    const float* h0  = (const float*)d_in[1];
    const float* c0  = (const float*)d_in[2];
    const float* Wih = (const float*)d_in[3];
    const float* Whh = (const float*)d_in[4];
    const float* bih = (const float*)d_in[5];
    const float* bhh = (const float*)d_in[6];
    float* out = (float*)d_out;

    const size_t total_elems = (size_t)BATCH * T_STEPS * HID + 2 * (size_t)BATCH * HID;
    const int write_tail = ((size_t)out_size >= total_elems) ? 1 : 0;

    const int rec_smem = 2 * 32 * HPAD * (int)sizeof(float);  // 132096 B (R2 exact)
    cudaFuncSetAttribute(lstm_rec_kernel, cudaFuncAttributeMaxDynamicSharedMemorySize,
                         rec_smem);

    // lazily created side stream + fork/join events (created once, outside capture)
    static cudaStream_t s2 = nullptr;
    static cudaEvent_t evFork = nullptr, evJoin = nullptr;
    if (s2 == nullptr) {
        cudaStreamCreateWithFlags(&s2, cudaStreamNonBlocking);
        cudaEventCreateWithFlags(&evFork, cudaEventDisableTiming);
        cudaEventCreateWithFlags(&evJoin, cudaEventDisableTiming);
    }

    // reset counters (captured nodes; run every replay)
    void* barAddr = nullptr;
    void* flagAddr = nullptr;
    cudaGetSymbolAddress(&barAddr, g_bar);
    cudaGetSymbolAddress(&flagAddr, g_xgflag);
    cudaMemsetAsync(barAddr, 0, sizeof(unsigned int));
    cudaMemsetAsync(flagAddr, 0, NCHUNK * sizeof(unsigned int));

    // fork: gemm on side stream, recurrence on main stream -> run CONCURRENTLY
    cudaEventRecord(evFork, 0);
    cudaStreamWaitEvent(s2, evFork, 0);

    dim3 g1(G4 / 64, NCHUNK);           // (32 n-tiles, 256 t-chunks)
    xg_gemm_kernel<<<g1, 256, 0, s2>>>(x, Wih, bih, bhh);
    cudaEventRecord(evJoin, s2);

    lstm_rec_kernel<<<NBLK, 256, rec_smem>>>(h0, c0, Whh, out, write_tail);

    // join the side branch back into the captured stream
    cudaStreamWaitEvent(0, evJoin, 0);
}